// round 15
// baseline (speedup 1.0000x reference)
#include <cuda_runtime.h>
#include <cuda_fp16.h>

#define BB 2
#define NN 65536
#define KK 16
#define DD 32
#define BBNN (BB * NN)

typedef unsigned long long u64;

__device__ __forceinline__ u64 pk2(float lo, float hi) {
    u64 r; asm("mov.b64 %0,{%1,%2};" : "=l"(r) : "f"(lo), "f"(hi)); return r;
}
__device__ __forceinline__ void up2(u64 v, float& a, float& b) {
    asm("mov.b64 {%0,%1},%2;" : "=f"(a), "=f"(b) : "l"(v));
}
__device__ __forceinline__ u64 ffma2(u64 a, u64 b, u64 c) {
    u64 d; asm("fma.rn.f32x2 %0,%1,%2,%3;" : "=l"(d) : "l"(a), "l"(b), "l"(c)); return d;
}

// Scratch (device globals; no allocation allowed)
__device__ uint4 g_preh4[BBNN * 4];      // pre[b][n][32] fp16 rows (8 MB, L2-resident)
__device__ int   g_partI[BB * 64];       // TNet channel maxima (int-bit fp, >=0)
__device__ int   g_idx64;                // 1 if neigh_idx is int64, else 0

// ---------------------------------------------------------------------------
// K0: zero the TNet max accumulator (values are >= 0, so 0-init is identity).
// ---------------------------------------------------------------------------
__global__ void k_zero() {
    int t = threadIdx.x;
    if (t < BB * 64) g_partI[t] = 0;
}

// ---------------------------------------------------------------------------
// K1: TNet pointwise 3->16->64 + max over 1024 pts/block (measured 13.8 us).
// ---------------------------------------------------------------------------
#define H1STR 1032
__global__ void __launch_bounds__(512) k_tnet_reduce(
    const float* __restrict__ xyz, const int* __restrict__ nidx,
    const float* __restrict__ tW1, const float* __restrict__ ts1, const float* __restrict__ tb1,
    const float* __restrict__ tW2, const float* __restrict__ ts2, const float* __restrict__ tb2)
{
    __shared__ float4 sW2f4[256];        // W2 16x64 as float4
    __shared__ float  sW1[48], sS1[16], sB1[16], sS2[64], sB2[64];
    __shared__ float  h1S[16 * H1STR];   // h1 tile [c][p], 1024 pts + pad
    __shared__ float  partS[32 * 64];    // per-ptgroup channel maxima
    int t = threadIdx.x;
    if (t < 256) sW2f4[t] = ((const float4*)tW2)[t];
    if (t < 48) sW1[t] = tW1[t];
    if (t < 16) { sS1[t] = ts1[t]; sB1[t] = tb1[t]; }
    if (t < 64) { sS2[t] = ts2[t]; sB2[t] = tb2[t]; }
    if (blockIdx.x == 0 && t == 0) {
        int z = 0;
#pragma unroll
        for (int i = 1; i < 16; i += 2) z |= nidx[i];
        g_idx64 = (z == 0) ? 1 : 0;
    }
    __syncthreads();

    // Phase A: h1 = relu((xyz @ tW1)*s1+b1), 2 points/thread -> smem
    int base = blockIdx.x * 1024;
#pragma unroll
    for (int r = 0; r < 2; r++) {
        int p  = r * 512 + t;
        int gp = base + p;
        float x0 = xyz[gp * 3 + 0], x1 = xyz[gp * 3 + 1], x2 = xyz[gp * 3 + 2];
#pragma unroll
        for (int c = 0; c < 16; c++) {
            float a = x0 * sW1[c] + x1 * sW1[16 + c] + x2 * sW1[32 + c];
            h1S[c * H1STR + p] = fmaxf(a * sS1[c] + sB1[c], 0.f);
        }
    }
    __syncthreads();

    // Phase B: h2 GEMM (16->64) + running max. Thread = (pt-group, 4ch).
    int pg = t >> 4, g = t & 15;
    int c0 = g * 4;
    float s0 = sS2[c0], s1v = sS2[c0 + 1], s2v = sS2[c0 + 2], s3v = sS2[c0 + 3];
    float b0 = sB2[c0], b1v = sB2[c0 + 1], b2v = sB2[c0 + 2], b3v = sB2[c0 + 3];
    float4 m4 = make_float4(0.f, 0.f, 0.f, 0.f);   // m>=0 init => fmax == max-of-relu
#pragma unroll
    for (int q = 0; q < 8; q++) {
        int p0 = pg * 32 + q * 4;
        float4 a0 = make_float4(0.f, 0.f, 0.f, 0.f), a1 = a0, a2 = a0, a3 = a0;
#pragma unroll
        for (int k = 0; k < 16; k++) {
            float4 w = sW2f4[k * 16 + g];
            float4 f = *(const float4*)(h1S + k * H1STR + p0);
            a0.x += f.x * w.x; a0.y += f.x * w.y; a0.z += f.x * w.z; a0.w += f.x * w.w;
            a1.x += f.y * w.x; a1.y += f.y * w.y; a1.z += f.y * w.z; a1.w += f.y * w.w;
            a2.x += f.z * w.x; a2.y += f.z * w.y; a2.z += f.z * w.z; a2.w += f.z * w.w;
            a3.x += f.w * w.x; a3.y += f.w * w.y; a3.z += f.w * w.z; a3.w += f.w * w.w;
        }
        m4.x = fmaxf(m4.x, a0.x * s0 + b0);  m4.y = fmaxf(m4.y, a0.y * s1v + b1v);
        m4.z = fmaxf(m4.z, a0.z * s2v + b2v); m4.w = fmaxf(m4.w, a0.w * s3v + b3v);
        m4.x = fmaxf(m4.x, a1.x * s0 + b0);  m4.y = fmaxf(m4.y, a1.y * s1v + b1v);
        m4.z = fmaxf(m4.z, a1.z * s2v + b2v); m4.w = fmaxf(m4.w, a1.w * s3v + b3v);
        m4.x = fmaxf(m4.x, a2.x * s0 + b0);  m4.y = fmaxf(m4.y, a2.y * s1v + b1v);
        m4.z = fmaxf(m4.z, a2.z * s2v + b2v); m4.w = fmaxf(m4.w, a2.w * s3v + b3v);
        m4.x = fmaxf(m4.x, a3.x * s0 + b0);  m4.y = fmaxf(m4.y, a3.y * s1v + b1v);
        m4.z = fmaxf(m4.z, a3.z * s2v + b2v); m4.w = fmaxf(m4.w, a3.w * s3v + b3v);
    }
    *(float4*)(partS + pg * 64 + c0) = m4;
    __syncthreads();

    if (t < 64) {
        float v = partS[t];
#pragma unroll
        for (int pg2 = 1; pg2 < 32; pg2++) v = fmaxf(v, partS[pg2 * 64 + t]);
        int b = (blockIdx.x * 1024) >> 16;       // batch (uniform per block)
        atomicMax(&g_partI[b * 64 + t], __float_as_int(v));   // v >= 0
    }
}

// ---------------------------------------------------------------------------
// K3: fused per-point MLPs -> pre[b,n,32] fp16, TNet head inline (measured ~16us).
// ---------------------------------------------------------------------------
__global__ void __launch_bounds__(128) k_pointwise(
    const float* __restrict__ feature, const float* __restrict__ xyz,
    const float* __restrict__ tW3, const float* __restrict__ ts3, const float* __restrict__ tb3,
    const float* __restrict__ tW4, const float* __restrict__ tb4,
    const float* __restrict__ W1, const float* __restrict__ s1, const float* __restrict__ b1,
    const float* __restrict__ W2, const float* __restrict__ s2, const float* __restrict__ b2,
    const float* __restrict__ W3, const float* __restrict__ s3, const float* __restrict__ b3)
{
    __shared__ float4 sW2f4[256];        // W2 32x32
    __shared__ float4 sW3f4[256];        // W3 rows 0..31
    __shared__ float4 sW3x4[24];         // W3 rows 32..34 (xyz part)
    __shared__ float  sS2[32], sB2[32], sS3[32], sB3[32];
    __shared__ float  sW1[9], sTM[9], sS1[3], sB1[3];
    __shared__ float  hmax[64], h3s[16];
    __shared__ uint4  sStage[640];       // pre stage: 128 pts x 4 uint4, stride 5
    int t   = threadIdx.x;
    int gp0 = blockIdx.x * 128;
    int b   = gp0 >> 16;
    { const float4* W2v = (const float4*)W2;
      sW2f4[t] = W2v[t]; sW2f4[128 + t] = W2v[128 + t]; }
    { const float4* W3v = (const float4*)W3;
      sW3f4[t] = W3v[t]; sW3f4[128 + t] = W3v[128 + t];
      if (t < 24) sW3x4[t] = W3v[256 + t]; }
    if (t < 32) { sS2[t] = s2[t]; sB2[t] = b2[t]; sS3[t] = s3[t]; sB3[t] = b3[t]; }
    if (t < 9)  sW1[t] = W1[t];
    if (t < 3)  { sS1[t] = s1[t]; sB1[t] = b1[t]; }
    // TNet head, inline: hmax (direct read) -> h3 -> tmat
    if (t >= 64 && t < 128) {
        int c = t - 64;
        hmax[c] = __int_as_float(g_partI[b * 64 + c]);
    }
    __syncthreads();
    if (t < 16) {
        float a = 0.f;
#pragma unroll
        for (int i = 0; i < 64; i++) a += hmax[i] * tW3[i * 16 + t];
        h3s[t] = fmaxf(a * ts3[t] + tb3[t], 0.f);
    }
    __syncthreads();
    if (t < 9) {
        float a = 0.f;
#pragma unroll
        for (int i = 0; i < 16; i++) a += h3s[i] * tW4[i * 9 + t];
        a += tb4[t];
        if (t == 0 || t == 4 || t == 8) a += 1.0f;   // + eye(3)
        sTM[t] = a;
    }
    __syncthreads();

    int gp = gp0 + t;
    int n  = gp & (NN - 1);

    // f_xyz = relu(((xyz @ t3x3) @ W1) * s1 + b1)
    float x0 = xyz[gp * 3 + 0], x1 = xyz[gp * 3 + 1], x2 = xyz[gp * 3 + 2];
    float v0 = x0 * sTM[0] + x1 * sTM[3] + x2 * sTM[6];
    float v1 = x0 * sTM[1] + x1 * sTM[4] + x2 * sTM[7];
    float v2 = x0 * sTM[2] + x1 * sTM[5] + x2 * sTM[8];
    float fx0 = fmaxf((v0 * sW1[0] + v1 * sW1[3] + v2 * sW1[6]) * sS1[0] + sB1[0], 0.f);
    float fx1 = fmaxf((v0 * sW1[1] + v1 * sW1[4] + v2 * sW1[7]) * sS1[1] + sB1[1], 0.f);
    float fx2 = fmaxf((v0 * sW1[2] + v1 * sW1[5] + v2 * sW1[8]) * sS1[2] + sB1[2], 0.f);

    // f_nei = relu((feat @ W2) * s2 + b2)
    const float* fbase = feature + (size_t)b * DD * NN + n;
    float acc[32];
#pragma unroll
    for (int c = 0; c < 32; c++) acc[c] = 0.f;
#pragma unroll
    for (int i = 0; i < 32; i++) {
        float v = fbase[(size_t)i * NN];
#pragma unroll
        for (int c4 = 0; c4 < 8; c4++) {
            float4 w = sW2f4[i * 8 + c4];
            acc[c4 * 4 + 0] += v * w.x; acc[c4 * 4 + 1] += v * w.y;
            acc[c4 * 4 + 2] += v * w.z; acc[c4 * 4 + 3] += v * w.w;
        }
    }
    float fn[32];
#pragma unroll
    for (int c = 0; c < 32; c++) fn[c] = fmaxf(acc[c] * sS2[c] + sB2[c], 0.f);

    // pre = relu((concat(fn, fx) @ W3) * s3 + b3)
#pragma unroll
    for (int c = 0; c < 32; c++) acc[c] = 0.f;
#pragma unroll
    for (int i = 0; i < 32; i++) {
        float v = fn[i];
#pragma unroll
        for (int c4 = 0; c4 < 8; c4++) {
            float4 w = sW3f4[i * 8 + c4];
            acc[c4 * 4 + 0] += v * w.x; acc[c4 * 4 + 1] += v * w.y;
            acc[c4 * 4 + 2] += v * w.z; acc[c4 * 4 + 3] += v * w.w;
        }
    }
#pragma unroll
    for (int c4 = 0; c4 < 8; c4++) {
        float4 wa = sW3x4[c4], wb = sW3x4[8 + c4], wc = sW3x4[16 + c4];
        acc[c4 * 4 + 0] += fx0 * wa.x + fx1 * wb.x + fx2 * wc.x;
        acc[c4 * 4 + 1] += fx0 * wa.y + fx1 * wb.y + fx2 * wc.y;
        acc[c4 * 4 + 2] += fx0 * wa.z + fx1 * wb.z + fx2 * wc.z;
        acc[c4 * 4 + 3] += fx0 * wa.w + fx1 * wb.w + fx2 * wc.w;
    }
    unsigned uh[16];
#pragma unroll
    for (int c2 = 0; c2 < 16; c2++) {
        float a  = fmaxf(acc[2 * c2]     * sS3[2 * c2]     + sB3[2 * c2],     0.f);
        float bb = fmaxf(acc[2 * c2 + 1] * sS3[2 * c2 + 1] + sB3[2 * c2 + 1], 0.f);
        __half2 h = __floats2half2_rn(a, bb);
        uh[c2] = *reinterpret_cast<unsigned*>(&h);
    }
#pragma unroll
    for (int q = 0; q < 4; q++) {
        uint4 o;
        o.x = uh[q * 4 + 0]; o.y = uh[q * 4 + 1]; o.z = uh[q * 4 + 2]; o.w = uh[q * 4 + 3];
        sStage[t * 5 + q] = o;
    }
    __syncthreads();

    // coalesced uint4 writeout of pre
    uint4* outp = g_preh4 + (size_t)gp0 * 4;
#pragma unroll
    for (int r = 0; r < 4; r++) {
        int i = r * 128 + t;             // i = p*4 + q
        outp[i] = sStage[(i >> 2) * 5 + (i & 3)];
    }
}

// ---------------------------------------------------------------------------
// K4 (v4): channel-major. No featS staging (MLP reads feature directly as
// packed f32x2 pairs), zero-MOV FFMA2 mainloop (pre-duplicated weight pairs),
// direct STG.128 epilogue. 128 pts/block x 256 threads, ~34KB smem.
// ---------------------------------------------------------------------------
__global__ void __launch_bounds__(256) k_gather_final(
    const float* __restrict__ feature, const int* __restrict__ nidx,
    const float* __restrict__ W4, const float* __restrict__ s4, const float* __restrict__ b4,
    float* __restrict__ out)
{
    __shared__ u64   w2S[64 * 32];       // W4 as duplicated (w,w) pairs, [i][c]
    __shared__ float fcatS[32 * 132];    // fcat [c][p], stride 132
    __shared__ float sS4[32], sB4[32];
    int t = threadIdx.x;
    // stage duplicated weights: each thread expands 8 scalars
    {
        const float4* W4v = (const float4*)W4;   // 512 float4 total
        float4 wa = W4v[t * 2], wb = W4v[t * 2 + 1];
        u64* dst = w2S + t * 8;
        dst[0] = pk2(wa.x, wa.x); dst[1] = pk2(wa.y, wa.y);
        dst[2] = pk2(wa.z, wa.z); dst[3] = pk2(wa.w, wa.w);
        dst[4] = pk2(wb.x, wb.x); dst[5] = pk2(wb.y, wb.y);
        dst[6] = pk2(wb.z, wb.z); dst[7] = pk2(wb.w, wb.w);
    }
    if (t < 32) { sS4[t] = s4[t]; sB4[t] = b4[t]; }

    int gp0 = blockIdx.x * 128;
    int b   = gp0 >> 16;
    int n0  = gp0 & (NN - 1);

    // cooperative gather-max: 4 lanes/point, 2 passes of 64 points
    {
        int lane = t & 31;
        int warp = t >> 5;               // 0..7
        int cl   = lane & 3;
        int mul  = g_idx64 ? 2 : 1;
        const uint4* pre4 = g_preh4 + (size_t)b * NN * 4;
#pragma unroll
        for (int r = 0; r < 2; r++) {
            int p  = r * 64 + warp * 8 + (lane >> 2);
            int gp = gp0 + p;
            const int* ib = nidx + (size_t)gp * KK * mul;
            int j0 = ib[cl * mul];
            int j1 = ib[(cl + 4) * mul];
            int j2 = ib[(cl + 8) * mul];
            int j3 = ib[(cl + 12) * mul];
            __half2 a0 = __half2half2(__ushort_as_half(0));
            __half2 a1 = a0, a2 = a0, a3 = a0;   // pre >= 0, so 0-init exact
#pragma unroll
            for (int k = 0; k < KK; k++) {
                int jr = (k < 8) ? ((k < 4) ? j0 : j1) : ((k < 12) ? j2 : j3);
                int j  = __shfl_sync(0xffffffffu, jr, k & 3, 4);
                uint4 v = pre4[(size_t)j * 4 + cl];
                a0 = __hmax2(a0, *reinterpret_cast<__half2*>(&v.x));
                a1 = __hmax2(a1, *reinterpret_cast<__half2*>(&v.y));
                a2 = __hmax2(a2, *reinterpret_cast<__half2*>(&v.z));
                a3 = __hmax2(a3, *reinterpret_cast<__half2*>(&v.w));
            }
            float2 f0 = __half22float2(a0), f1 = __half22float2(a1);
            float2 f2 = __half22float2(a2), f3 = __half22float2(a3);
            int cb = cl * 8;             // channel-major scatter (stride 132)
            fcatS[(cb + 0) * 132 + p] = f0.x; fcatS[(cb + 1) * 132 + p] = f0.y;
            fcatS[(cb + 2) * 132 + p] = f1.x; fcatS[(cb + 3) * 132 + p] = f1.y;
            fcatS[(cb + 4) * 132 + p] = f2.x; fcatS[(cb + 5) * 132 + p] = f2.y;
            fcatS[(cb + 6) * 132 + p] = f3.x; fcatS[(cb + 7) * 132 + p] = f3.y;
        }
    }
    __syncthreads();

    // MLP: thread = (4 points, 4 channels), K=64. Inputs arrive as packed
    // f32x2 point-pairs (ulonglong2 loads), weights as duplicated pairs.
    int pq = t >> 3, g = t & 7;          // pq: 0..31, g: 0..7
    int p0 = pq * 4, c0 = g * 4;
    u64 a0[4] = {0ull, 0ull, 0ull, 0ull};   // pts (p0,p0+1), ch c0..c3
    u64 a1[4] = {0ull, 0ull, 0ull, 0ull};   // pts (p0+2,p0+3)
    const float* fg = feature + (size_t)b * DD * NN + n0 + p0;
#pragma unroll
    for (int i = 0; i < 32; i++) {       // feat half (direct gmem, L1/L2-hot)
        ulonglong2 f = *(const ulonglong2*)(fg + (size_t)i * NN);
        const u64* w = w2S + i * 32 + c0;
        ulonglong2 wA = *(const ulonglong2*)w;
        ulonglong2 wB = *(const ulonglong2*)(w + 2);
        a0[0] = ffma2(f.x, wA.x, a0[0]); a1[0] = ffma2(f.y, wA.x, a1[0]);
        a0[1] = ffma2(f.x, wA.y, a0[1]); a1[1] = ffma2(f.y, wA.y, a1[1]);
        a0[2] = ffma2(f.x, wB.x, a0[2]); a1[2] = ffma2(f.y, wB.x, a1[2]);
        a0[3] = ffma2(f.x, wB.y, a0[3]); a1[3] = ffma2(f.y, wB.y, a1[3]);
    }
#pragma unroll
    for (int i = 0; i < 32; i++) {       // fcat half (smem, conflict-free pairs)
        ulonglong2 f = *(const ulonglong2*)(fcatS + i * 132 + p0);
        const u64* w = w2S + (32 + i) * 32 + c0;
        ulonglong2 wA = *(const ulonglong2*)w;
        ulonglong2 wB = *(const ulonglong2*)(w + 2);
        a0[0] = ffma2(f.x, wA.x, a0[0]); a1[0] = ffma2(f.y, wA.x, a1[0]);
        a0[1] = ffma2(f.x, wA.y, a0[1]); a1[1] = ffma2(f.y, wA.y, a1[1]);
        a0[2] = ffma2(f.x, wB.x, a0[2]); a1[2] = ffma2(f.y, wB.x, a1[2]);
        a0[3] = ffma2(f.x, wB.y, a0[3]); a1[3] = ffma2(f.y, wB.y, a1[3]);
    }

    // epilogue: scale+bias+relu, direct STG.128 (channel-major output)
    float* ob = out + (size_t)b * DD * NN + n0 + p0;
#pragma unroll
    for (int c = 0; c < 4; c++) {
        float s = sS4[c0 + c], bi = sB4[c0 + c];
        float x0, x1, x2, x3;
        up2(a0[c], x0, x1);
        up2(a1[c], x2, x3);
        float4 o = make_float4(fmaxf(x0 * s + bi, 0.f), fmaxf(x1 * s + bi, 0.f),
                               fmaxf(x2 * s + bi, 0.f), fmaxf(x3 * s + bi, 0.f));
        *(float4*)(ob + (size_t)(c0 + c) * NN) = o;
    }
}

// ---------------------------------------------------------------------------

extern "C" void kernel_launch(void* const* d_in, const int* in_sizes, int n_in,
                              void* d_out, int out_size) {
    const float* feature = (const float*)d_in[0];
    const float* xyz     = (const float*)d_in[1];
    const int*   nidx    = (const int*)d_in[2];
    const float* tW1 = (const float*)d_in[3];  const float* ts1 = (const float*)d_in[4];  const float* tb1 = (const float*)d_in[5];
    const float* tW2 = (const float*)d_in[6];  const float* ts2 = (const float*)d_in[7];  const float* tb2 = (const float*)d_in[8];
    const float* tW3 = (const float*)d_in[9];  const float* ts3 = (const float*)d_in[10]; const float* tb3 = (const float*)d_in[11];
    const float* tW4 = (const float*)d_in[12]; const float* tb4 = (const float*)d_in[13];
    const float* W1  = (const float*)d_in[14]; const float* s1  = (const float*)d_in[15]; const float* b1  = (const float*)d_in[16];
    const float* W2  = (const float*)d_in[17]; const float* s2  = (const float*)d_in[18]; const float* b2  = (const float*)d_in[19];
    const float* W3  = (const float*)d_in[20]; const float* s3  = (const float*)d_in[21]; const float* b3  = (const float*)d_in[22];
    const float* W4  = (const float*)d_in[23]; const float* s4  = (const float*)d_in[24]; const float* b4  = (const float*)d_in[25];
    float* out = (float*)d_out;

    k_zero<<<1, 128>>>();
    k_tnet_reduce<<<128, 512>>>(xyz, nidx, tW1, ts1, tb1, tW2, ts2, tb2);
    k_pointwise<<<(BB * NN) / 128, 128>>>(feature, xyz, tW3, ts3, tb3, tW4, tb4,
                                          W1, s1, b1, W2, s2, b2, W3, s3, b3);
    k_gather_final<<<(BB * NN) / 128, 256>>>(feature, nidx, W4, s4, b4, out);
}

// round 16
// speedup vs baseline: 1.3830x; 1.3830x over previous
#include <cuda_runtime.h>
#include <cuda_fp16.h>

#define BB 2
#define NN 65536
#define KK 16
#define DD 32
#define BBNN (BB * NN)

typedef unsigned long long u64;

__device__ __forceinline__ u64 pk2(float lo, float hi) {
    u64 r; asm("mov.b64 %0,{%1,%2};" : "=l"(r) : "f"(lo), "f"(hi)); return r;
}
__device__ __forceinline__ void up2(u64 v, float& a, float& b) {
    asm("mov.b64 {%0,%1},%2;" : "=f"(a), "=f"(b) : "l"(v));
}
__device__ __forceinline__ u64 ffma2(u64 a, u64 b, u64 c) {
    u64 d; asm("fma.rn.f32x2 %0,%1,%2,%3;" : "=l"(d) : "l"(a), "l"(b), "l"(c)); return d;
}

// Scratch (device globals; no allocation allowed)
__device__ uint4 g_preh4[BBNN * 4];      // pre[b][n][32] fp16 rows (8 MB, L2-resident)
__device__ int   g_partI[BB * 64];       // TNet channel maxima (int-bit fp, >=0)
__device__ int   g_idx64;                // 1 if neigh_idx is int64, else 0

// ---------------------------------------------------------------------------
// K0: zero the TNet max accumulator (values are >= 0, so 0-init is identity).
// ---------------------------------------------------------------------------
__global__ void k_zero() {
    int t = threadIdx.x;
    if (t < BB * 64) g_partI[t] = 0;
}

// ---------------------------------------------------------------------------
// K1: TNet pointwise 3->16->64 + max over 1024 pts/block (measured 13.8 us).
// ---------------------------------------------------------------------------
#define H1STR 1032
__global__ void __launch_bounds__(512) k_tnet_reduce(
    const float* __restrict__ xyz, const int* __restrict__ nidx,
    const float* __restrict__ tW1, const float* __restrict__ ts1, const float* __restrict__ tb1,
    const float* __restrict__ tW2, const float* __restrict__ ts2, const float* __restrict__ tb2)
{
    __shared__ float4 sW2f4[256];        // W2 16x64 as float4
    __shared__ float  sW1[48], sS1[16], sB1[16], sS2[64], sB2[64];
    __shared__ float  h1S[16 * H1STR];   // h1 tile [c][p], 1024 pts + pad
    __shared__ float  partS[32 * 64];    // per-ptgroup channel maxima
    int t = threadIdx.x;
    if (t < 256) sW2f4[t] = ((const float4*)tW2)[t];
    if (t < 48) sW1[t] = tW1[t];
    if (t < 16) { sS1[t] = ts1[t]; sB1[t] = tb1[t]; }
    if (t < 64) { sS2[t] = ts2[t]; sB2[t] = tb2[t]; }
    if (blockIdx.x == 0 && t == 0) {
        int z = 0;
#pragma unroll
        for (int i = 1; i < 16; i += 2) z |= nidx[i];
        g_idx64 = (z == 0) ? 1 : 0;
    }
    __syncthreads();

    // Phase A: h1 = relu((xyz @ tW1)*s1+b1), 2 points/thread -> smem
    int base = blockIdx.x * 1024;
#pragma unroll
    for (int r = 0; r < 2; r++) {
        int p  = r * 512 + t;
        int gp = base + p;
        float x0 = xyz[gp * 3 + 0], x1 = xyz[gp * 3 + 1], x2 = xyz[gp * 3 + 2];
#pragma unroll
        for (int c = 0; c < 16; c++) {
            float a = x0 * sW1[c] + x1 * sW1[16 + c] + x2 * sW1[32 + c];
            h1S[c * H1STR + p] = fmaxf(a * sS1[c] + sB1[c], 0.f);
        }
    }
    __syncthreads();

    // Phase B: h2 GEMM (16->64) + running max. Thread = (pt-group, 4ch).
    int pg = t >> 4, g = t & 15;
    int c0 = g * 4;
    float s0 = sS2[c0], s1v = sS2[c0 + 1], s2v = sS2[c0 + 2], s3v = sS2[c0 + 3];
    float b0 = sB2[c0], b1v = sB2[c0 + 1], b2v = sB2[c0 + 2], b3v = sB2[c0 + 3];
    float4 m4 = make_float4(0.f, 0.f, 0.f, 0.f);   // m>=0 init => fmax == max-of-relu
#pragma unroll
    for (int q = 0; q < 8; q++) {
        int p0 = pg * 32 + q * 4;
        float4 a0 = make_float4(0.f, 0.f, 0.f, 0.f), a1 = a0, a2 = a0, a3 = a0;
#pragma unroll
        for (int k = 0; k < 16; k++) {
            float4 w = sW2f4[k * 16 + g];
            float4 f = *(const float4*)(h1S + k * H1STR + p0);
            a0.x += f.x * w.x; a0.y += f.x * w.y; a0.z += f.x * w.z; a0.w += f.x * w.w;
            a1.x += f.y * w.x; a1.y += f.y * w.y; a1.z += f.y * w.z; a1.w += f.y * w.w;
            a2.x += f.z * w.x; a2.y += f.z * w.y; a2.z += f.z * w.z; a2.w += f.z * w.w;
            a3.x += f.w * w.x; a3.y += f.w * w.y; a3.z += f.w * w.z; a3.w += f.w * w.w;
        }
        m4.x = fmaxf(m4.x, a0.x * s0 + b0);  m4.y = fmaxf(m4.y, a0.y * s1v + b1v);
        m4.z = fmaxf(m4.z, a0.z * s2v + b2v); m4.w = fmaxf(m4.w, a0.w * s3v + b3v);
        m4.x = fmaxf(m4.x, a1.x * s0 + b0);  m4.y = fmaxf(m4.y, a1.y * s1v + b1v);
        m4.z = fmaxf(m4.z, a1.z * s2v + b2v); m4.w = fmaxf(m4.w, a1.w * s3v + b3v);
        m4.x = fmaxf(m4.x, a2.x * s0 + b0);  m4.y = fmaxf(m4.y, a2.y * s1v + b1v);
        m4.z = fmaxf(m4.z, a2.z * s2v + b2v); m4.w = fmaxf(m4.w, a2.w * s3v + b3v);
        m4.x = fmaxf(m4.x, a3.x * s0 + b0);  m4.y = fmaxf(m4.y, a3.y * s1v + b1v);
        m4.z = fmaxf(m4.z, a3.z * s2v + b2v); m4.w = fmaxf(m4.w, a3.w * s3v + b3v);
    }
    *(float4*)(partS + pg * 64 + c0) = m4;
    __syncthreads();

    if (t < 64) {
        float v = partS[t];
#pragma unroll
        for (int pg2 = 1; pg2 < 32; pg2++) v = fmaxf(v, partS[pg2 * 64 + t]);
        int b = (blockIdx.x * 1024) >> 16;       // batch (uniform per block)
        atomicMax(&g_partI[b * 64 + t], __float_as_int(v));   // v >= 0
    }
}

// ---------------------------------------------------------------------------
// K3: fused per-point MLPs -> pre[b,n,32] fp16, TNet head inline (measured ~16us).
// ---------------------------------------------------------------------------
__global__ void __launch_bounds__(128) k_pointwise(
    const float* __restrict__ feature, const float* __restrict__ xyz,
    const float* __restrict__ tW3, const float* __restrict__ ts3, const float* __restrict__ tb3,
    const float* __restrict__ tW4, const float* __restrict__ tb4,
    const float* __restrict__ W1, const float* __restrict__ s1, const float* __restrict__ b1,
    const float* __restrict__ W2, const float* __restrict__ s2, const float* __restrict__ b2,
    const float* __restrict__ W3, const float* __restrict__ s3, const float* __restrict__ b3)
{
    __shared__ float4 sW2f4[256];        // W2 32x32
    __shared__ float4 sW3f4[256];        // W3 rows 0..31
    __shared__ float4 sW3x4[24];         // W3 rows 32..34 (xyz part)
    __shared__ float  sS2[32], sB2[32], sS3[32], sB3[32];
    __shared__ float  sW1[9], sTM[9], sS1[3], sB1[3];
    __shared__ float  hmax[64], h3s[16];
    __shared__ uint4  sStage[640];       // pre stage: 128 pts x 4 uint4, stride 5
    int t   = threadIdx.x;
    int gp0 = blockIdx.x * 128;
    int b   = gp0 >> 16;
    { const float4* W2v = (const float4*)W2;
      sW2f4[t] = W2v[t]; sW2f4[128 + t] = W2v[128 + t]; }
    { const float4* W3v = (const float4*)W3;
      sW3f4[t] = W3v[t]; sW3f4[128 + t] = W3v[128 + t];
      if (t < 24) sW3x4[t] = W3v[256 + t]; }
    if (t < 32) { sS2[t] = s2[t]; sB2[t] = b2[t]; sS3[t] = s3[t]; sB3[t] = b3[t]; }
    if (t < 9)  sW1[t] = W1[t];
    if (t < 3)  { sS1[t] = s1[t]; sB1[t] = b1[t]; }
    // TNet head, inline: hmax (direct read) -> h3 -> tmat
    if (t >= 64 && t < 128) {
        int c = t - 64;
        hmax[c] = __int_as_float(g_partI[b * 64 + c]);
    }
    __syncthreads();
    if (t < 16) {
        float a = 0.f;
#pragma unroll
        for (int i = 0; i < 64; i++) a += hmax[i] * tW3[i * 16 + t];
        h3s[t] = fmaxf(a * ts3[t] + tb3[t], 0.f);
    }
    __syncthreads();
    if (t < 9) {
        float a = 0.f;
#pragma unroll
        for (int i = 0; i < 16; i++) a += h3s[i] * tW4[i * 9 + t];
        a += tb4[t];
        if (t == 0 || t == 4 || t == 8) a += 1.0f;   // + eye(3)
        sTM[t] = a;
    }
    __syncthreads();

    int gp = gp0 + t;
    int n  = gp & (NN - 1);

    // f_xyz = relu(((xyz @ t3x3) @ W1) * s1 + b1)
    float x0 = xyz[gp * 3 + 0], x1 = xyz[gp * 3 + 1], x2 = xyz[gp * 3 + 2];
    float v0 = x0 * sTM[0] + x1 * sTM[3] + x2 * sTM[6];
    float v1 = x0 * sTM[1] + x1 * sTM[4] + x2 * sTM[7];
    float v2 = x0 * sTM[2] + x1 * sTM[5] + x2 * sTM[8];
    float fx0 = fmaxf((v0 * sW1[0] + v1 * sW1[3] + v2 * sW1[6]) * sS1[0] + sB1[0], 0.f);
    float fx1 = fmaxf((v0 * sW1[1] + v1 * sW1[4] + v2 * sW1[7]) * sS1[1] + sB1[1], 0.f);
    float fx2 = fmaxf((v0 * sW1[2] + v1 * sW1[5] + v2 * sW1[8]) * sS1[2] + sB1[2], 0.f);

    // f_nei = relu((feat @ W2) * s2 + b2)
    const float* fbase = feature + (size_t)b * DD * NN + n;
    float acc[32];
#pragma unroll
    for (int c = 0; c < 32; c++) acc[c] = 0.f;
#pragma unroll
    for (int i = 0; i < 32; i++) {
        float v = fbase[(size_t)i * NN];
#pragma unroll
        for (int c4 = 0; c4 < 8; c4++) {
            float4 w = sW2f4[i * 8 + c4];
            acc[c4 * 4 + 0] += v * w.x; acc[c4 * 4 + 1] += v * w.y;
            acc[c4 * 4 + 2] += v * w.z; acc[c4 * 4 + 3] += v * w.w;
        }
    }
    float fn[32];
#pragma unroll
    for (int c = 0; c < 32; c++) fn[c] = fmaxf(acc[c] * sS2[c] + sB2[c], 0.f);

    // pre = relu((concat(fn, fx) @ W3) * s3 + b3)
#pragma unroll
    for (int c = 0; c < 32; c++) acc[c] = 0.f;
#pragma unroll
    for (int i = 0; i < 32; i++) {
        float v = fn[i];
#pragma unroll
        for (int c4 = 0; c4 < 8; c4++) {
            float4 w = sW3f4[i * 8 + c4];
            acc[c4 * 4 + 0] += v * w.x; acc[c4 * 4 + 1] += v * w.y;
            acc[c4 * 4 + 2] += v * w.z; acc[c4 * 4 + 3] += v * w.w;
        }
    }
#pragma unroll
    for (int c4 = 0; c4 < 8; c4++) {
        float4 wa = sW3x4[c4], wb = sW3x4[8 + c4], wc = sW3x4[16 + c4];
        acc[c4 * 4 + 0] += fx0 * wa.x + fx1 * wb.x + fx2 * wc.x;
        acc[c4 * 4 + 1] += fx0 * wa.y + fx1 * wb.y + fx2 * wc.y;
        acc[c4 * 4 + 2] += fx0 * wa.z + fx1 * wb.z + fx2 * wc.z;
        acc[c4 * 4 + 3] += fx0 * wa.w + fx1 * wb.w + fx2 * wc.w;
    }
    unsigned uh[16];
#pragma unroll
    for (int c2 = 0; c2 < 16; c2++) {
        float a  = fmaxf(acc[2 * c2]     * sS3[2 * c2]     + sB3[2 * c2],     0.f);
        float bb = fmaxf(acc[2 * c2 + 1] * sS3[2 * c2 + 1] + sB3[2 * c2 + 1], 0.f);
        __half2 h = __floats2half2_rn(a, bb);
        uh[c2] = *reinterpret_cast<unsigned*>(&h);
    }
#pragma unroll
    for (int q = 0; q < 4; q++) {
        uint4 o;
        o.x = uh[q * 4 + 0]; o.y = uh[q * 4 + 1]; o.z = uh[q * 4 + 2]; o.w = uh[q * 4 + 3];
        sStage[t * 5 + q] = o;
    }
    __syncthreads();

    // coalesced uint4 writeout of pre
    uint4* outp = g_preh4 + (size_t)gp0 * 4;
#pragma unroll
    for (int r = 0; r < 4; r++) {
        int i = r * 128 + t;             // i = p*4 + q
        outp[i] = sStage[(i >> 2) * 5 + (i & 3)];
    }
}

// ---------------------------------------------------------------------------
// K4 (v5): R14 structure (featS+fcatS staging, 4pt x 4ch MLP, 128 pts/block,
// 256 threads, 2 blocks/SM) with a direct STG.128 epilogue: each channel's
// 4 consecutive-point outputs are one 16B store. sOut staging + sync removed.
// ---------------------------------------------------------------------------
__global__ void __launch_bounds__(256) k_gather_final(
    const float* __restrict__ feature, const int* __restrict__ nidx,
    const float* __restrict__ W4, const float* __restrict__ s4, const float* __restrict__ b4,
    float* __restrict__ out)
{
    __shared__ float4 sW4f4[512];        // W4 64x32 (rows 0..31 feat, 32..63 fcat)
    __shared__ float  sS4[32], sB4[32];
    __shared__ float  featS[128 * 36];   // feat rows
    __shared__ float  fcatS[128 * 36];   // max-pooled rows
    int t = threadIdx.x;
    sW4f4[t] = ((const float4*)W4)[t];
    sW4f4[256 + t] = ((const float4*)W4)[256 + t];
    if (t < 32) { sS4[t] = s4[t]; sB4[t] = b4[t]; }

    int gp0 = blockIdx.x * 128;
    int b   = gp0 >> 16;
    int n0  = gp0 & (NN - 1);

    // stage feat (coalesced along n)
    const float* fbase = feature + (size_t)b * DD * NN + n0;
#pragma unroll
    for (int r = 0; r < 16; r++) {
        int i = r * 256 + t;             // i = c*128 + p
        int c = i >> 7, p = i & 127;
        featS[p * 36 + c] = fbase[(size_t)c * NN + p];
    }

    // cooperative gather-max: 4 lanes/point, 2 passes of 64 points
    {
        int lane = t & 31;
        int warp = t >> 5;               // 0..7
        int cl   = lane & 3;
        int mul  = g_idx64 ? 2 : 1;
        const uint4* pre4 = g_preh4 + (size_t)b * NN * 4;
#pragma unroll
        for (int r = 0; r < 2; r++) {
            int p  = r * 64 + warp * 8 + (lane >> 2);
            int gp = gp0 + p;
            const int* ib = nidx + (size_t)gp * KK * mul;
            int j0 = ib[cl * mul];
            int j1 = ib[(cl + 4) * mul];
            int j2 = ib[(cl + 8) * mul];
            int j3 = ib[(cl + 12) * mul];
            __half2 a0 = __half2half2(__ushort_as_half(0));
            __half2 a1 = a0, a2 = a0, a3 = a0;   // pre >= 0, so 0-init exact
#pragma unroll
            for (int k = 0; k < KK; k++) {
                int jr = (k < 8) ? ((k < 4) ? j0 : j1) : ((k < 12) ? j2 : j3);
                int j  = __shfl_sync(0xffffffffu, jr, k & 3, 4);
                uint4 v = pre4[(size_t)j * 4 + cl];
                a0 = __hmax2(a0, *reinterpret_cast<__half2*>(&v.x));
                a1 = __hmax2(a1, *reinterpret_cast<__half2*>(&v.y));
                a2 = __hmax2(a2, *reinterpret_cast<__half2*>(&v.z));
                a3 = __hmax2(a3, *reinterpret_cast<__half2*>(&v.w));
            }
            float2 f0 = __half22float2(a0), f1 = __half22float2(a1);
            float2 f2 = __half22float2(a2), f3 = __half22float2(a3);
            float4* row = (float4*)(fcatS + p * 36);
            row[cl * 2 + 0] = make_float4(f0.x, f0.y, f1.x, f1.y);
            row[cl * 2 + 1] = make_float4(f2.x, f2.y, f3.x, f3.y);
        }
    }
    __syncthreads();

    // MLP: thread = (4 consecutive points, 4 channels), K=64 (feat + fcat).
    int pq = t >> 3, g = t & 7;          // pq: 0..31, 4 points each
    int p0 = pq * 4;
    u64 aLo[4] = {0ull, 0ull, 0ull, 0ull}, aHi[4] = {0ull, 0ull, 0ull, 0ull};
    {
        const ulonglong2* w4u = (const ulonglong2*)sW4f4;
#pragma unroll
        for (int i4 = 0; i4 < 16; i4++) {
            ulonglong2 w0 = w4u[(i4 * 4 + 0) * 8 + g];
            ulonglong2 w1 = w4u[(i4 * 4 + 1) * 8 + g];
            ulonglong2 w2 = w4u[(i4 * 4 + 2) * 8 + g];
            ulonglong2 w3 = w4u[(i4 * 4 + 3) * 8 + g];
            const float* src = (i4 < 8) ? featS : fcatS;
            int i4r = (i4 < 8) ? i4 : (i4 - 8);
#pragma unroll
            for (int q = 0; q < 4; q++) {
                float4 f = ((const float4*)(src + (p0 + q) * 36))[i4r];
                u64 v;
                v = pk2(f.x, f.x); aLo[q] = ffma2(v, w0.x, aLo[q]); aHi[q] = ffma2(v, w0.y, aHi[q]);
                v = pk2(f.y, f.y); aLo[q] = ffma2(v, w1.x, aLo[q]); aHi[q] = ffma2(v, w1.y, aHi[q]);
                v = pk2(f.z, f.z); aLo[q] = ffma2(v, w2.x, aLo[q]); aHi[q] = ffma2(v, w2.y, aHi[q]);
                v = pk2(f.w, f.w); aLo[q] = ffma2(v, w3.x, aLo[q]); aHi[q] = ffma2(v, w3.y, aHi[q]);
            }
        }
    }

    // epilogue: unpack to (channel x 4 points), scale+bias+relu, STG.128
    {
        int c0 = g * 4;
        float x[4][4];
#pragma unroll
        for (int q = 0; q < 4; q++) {
            up2(aLo[q], x[q][0], x[q][1]);
            up2(aHi[q], x[q][2], x[q][3]);
        }
        float* ob = out + (size_t)b * DD * NN + n0 + p0;
#pragma unroll
        for (int c = 0; c < 4; c++) {
            float s = sS4[c0 + c], bi = sB4[c0 + c];
            float4 o = make_float4(fmaxf(x[0][c] * s + bi, 0.f),
                                   fmaxf(x[1][c] * s + bi, 0.f),
                                   fmaxf(x[2][c] * s + bi, 0.f),
                                   fmaxf(x[3][c] * s + bi, 0.f));
            *(float4*)(ob + (size_t)(c0 + c) * NN) = o;
        }
    }
}

// ---------------------------------------------------------------------------

extern "C" void kernel_launch(void* const* d_in, const int* in_sizes, int n_in,
                              void* d_out, int out_size) {
    const float* feature = (const float*)d_in[0];
    const float* xyz     = (const float*)d_in[1];
    const int*   nidx    = (const int*)d_in[2];
    const float* tW1 = (const float*)d_in[3];  const float* ts1 = (const float*)d_in[4];  const float* tb1 = (const float*)d_in[5];
    const float* tW2 = (const float*)d_in[6];  const float* ts2 = (const float*)d_in[7];  const float* tb2 = (const float*)d_in[8];
    const float* tW3 = (const float*)d_in[9];  const float* ts3 = (const float*)d_in[10]; const float* tb3 = (const float*)d_in[11];
    const float* tW4 = (const float*)d_in[12]; const float* tb4 = (const float*)d_in[13];
    const float* W1  = (const float*)d_in[14]; const float* s1  = (const float*)d_in[15]; const float* b1  = (const float*)d_in[16];
    const float* W2  = (const float*)d_in[17]; const float* s2  = (const float*)d_in[18]; const float* b2  = (const float*)d_in[19];
    const float* W3  = (const float*)d_in[20]; const float* s3  = (const float*)d_in[21]; const float* b3  = (const float*)d_in[22];
    const float* W4  = (const float*)d_in[23]; const float* s4  = (const float*)d_in[24]; const float* b4  = (const float*)d_in[25];
    float* out = (float*)d_out;

    k_zero<<<1, 128>>>();
    k_tnet_reduce<<<128, 512>>>(xyz, nidx, tW1, ts1, tb1, tW2, ts2, tb2);
    k_pointwise<<<(BB * NN) / 128, 128>>>(feature, xyz, tW3, ts3, tb3, tW4, tb4,
                                          W1, s1, b1, W2, s2, b2, W3, s3, b3);
    k_gather_final<<<(BB * NN) / 128, 256>>>(feature, nidx, W4, s4, b4, out);
}

// round 17
// speedup vs baseline: 1.3844x; 1.0010x over previous
#include <cuda_runtime.h>
#include <cuda_fp16.h>

#define BB 2
#define NN 65536
#define KK 16
#define DD 32
#define BBNN (BB * NN)

typedef unsigned long long u64;

__device__ __forceinline__ u64 pk2(float lo, float hi) {
    u64 r; asm("mov.b64 %0,{%1,%2};" : "=l"(r) : "f"(lo), "f"(hi)); return r;
}
__device__ __forceinline__ void up2(u64 v, float& a, float& b) {
    asm("mov.b64 {%0,%1},%2;" : "=f"(a), "=f"(b) : "l"(v));
}
__device__ __forceinline__ u64 ffma2(u64 a, u64 b, u64 c) {
    u64 d; asm("fma.rn.f32x2 %0,%1,%2,%3;" : "=l"(d) : "l"(a), "l"(b), "l"(c)); return d;
}

// Scratch (device globals; no allocation allowed)
__device__ uint4 g_preh4[BBNN * 4];      // pre[b][n][32] fp16 rows (8 MB, L2-resident)
__device__ int   g_partI[BB * 64];       // TNet channel maxima (int-bit fp, >=0)
__device__ int   g_idx64;                // 1 if neigh_idx is int64, else 0

// ---------------------------------------------------------------------------
// K0: zero the TNet max accumulator (values are >= 0, so 0-init is identity).
// ---------------------------------------------------------------------------
__global__ void k_zero() {
    int t = threadIdx.x;
    if (t < BB * 64) g_partI[t] = 0;
}

// ---------------------------------------------------------------------------
// K1: TNet pointwise 3->16->64 + max over 1024 pts/block (measured 13.8 us).
// ---------------------------------------------------------------------------
#define H1STR 1032
__global__ void __launch_bounds__(512) k_tnet_reduce(
    const float* __restrict__ xyz, const int* __restrict__ nidx,
    const float* __restrict__ tW1, const float* __restrict__ ts1, const float* __restrict__ tb1,
    const float* __restrict__ tW2, const float* __restrict__ ts2, const float* __restrict__ tb2)
{
    __shared__ float4 sW2f4[256];        // W2 16x64 as float4
    __shared__ float  sW1[48], sS1[16], sB1[16], sS2[64], sB2[64];
    __shared__ float  h1S[16 * H1STR];   // h1 tile [c][p], 1024 pts + pad
    __shared__ float  partS[32 * 64];    // per-ptgroup channel maxima
    int t = threadIdx.x;
    if (t < 256) sW2f4[t] = ((const float4*)tW2)[t];
    if (t < 48) sW1[t] = tW1[t];
    if (t < 16) { sS1[t] = ts1[t]; sB1[t] = tb1[t]; }
    if (t < 64) { sS2[t] = ts2[t]; sB2[t] = tb2[t]; }
    if (blockIdx.x == 0 && t == 0) {
        int z = 0;
#pragma unroll
        for (int i = 1; i < 16; i += 2) z |= nidx[i];
        g_idx64 = (z == 0) ? 1 : 0;
    }
    __syncthreads();

    // Phase A: h1 = relu((xyz @ tW1)*s1+b1), 2 points/thread -> smem
    int base = blockIdx.x * 1024;
#pragma unroll
    for (int r = 0; r < 2; r++) {
        int p  = r * 512 + t;
        int gp = base + p;
        float x0 = xyz[gp * 3 + 0], x1 = xyz[gp * 3 + 1], x2 = xyz[gp * 3 + 2];
#pragma unroll
        for (int c = 0; c < 16; c++) {
            float a = x0 * sW1[c] + x1 * sW1[16 + c] + x2 * sW1[32 + c];
            h1S[c * H1STR + p] = fmaxf(a * sS1[c] + sB1[c], 0.f);
        }
    }
    __syncthreads();

    // Phase B: h2 GEMM (16->64) + running max. Thread = (pt-group, 4ch).
    int pg = t >> 4, g = t & 15;
    int c0 = g * 4;
    float s0 = sS2[c0], s1v = sS2[c0 + 1], s2v = sS2[c0 + 2], s3v = sS2[c0 + 3];
    float b0 = sB2[c0], b1v = sB2[c0 + 1], b2v = sB2[c0 + 2], b3v = sB2[c0 + 3];
    float4 m4 = make_float4(0.f, 0.f, 0.f, 0.f);   // m>=0 init => fmax == max-of-relu
#pragma unroll
    for (int q = 0; q < 8; q++) {
        int p0 = pg * 32 + q * 4;
        float4 a0 = make_float4(0.f, 0.f, 0.f, 0.f), a1 = a0, a2 = a0, a3 = a0;
#pragma unroll
        for (int k = 0; k < 16; k++) {
            float4 w = sW2f4[k * 16 + g];
            float4 f = *(const float4*)(h1S + k * H1STR + p0);
            a0.x += f.x * w.x; a0.y += f.x * w.y; a0.z += f.x * w.z; a0.w += f.x * w.w;
            a1.x += f.y * w.x; a1.y += f.y * w.y; a1.z += f.y * w.z; a1.w += f.y * w.w;
            a2.x += f.z * w.x; a2.y += f.z * w.y; a2.z += f.z * w.z; a2.w += f.z * w.w;
            a3.x += f.w * w.x; a3.y += f.w * w.y; a3.z += f.w * w.z; a3.w += f.w * w.w;
        }
        m4.x = fmaxf(m4.x, a0.x * s0 + b0);  m4.y = fmaxf(m4.y, a0.y * s1v + b1v);
        m4.z = fmaxf(m4.z, a0.z * s2v + b2v); m4.w = fmaxf(m4.w, a0.w * s3v + b3v);
        m4.x = fmaxf(m4.x, a1.x * s0 + b0);  m4.y = fmaxf(m4.y, a1.y * s1v + b1v);
        m4.z = fmaxf(m4.z, a1.z * s2v + b2v); m4.w = fmaxf(m4.w, a1.w * s3v + b3v);
        m4.x = fmaxf(m4.x, a2.x * s0 + b0);  m4.y = fmaxf(m4.y, a2.y * s1v + b1v);
        m4.z = fmaxf(m4.z, a2.z * s2v + b2v); m4.w = fmaxf(m4.w, a2.w * s3v + b3v);
        m4.x = fmaxf(m4.x, a3.x * s0 + b0);  m4.y = fmaxf(m4.y, a3.y * s1v + b1v);
        m4.z = fmaxf(m4.z, a3.z * s2v + b2v); m4.w = fmaxf(m4.w, a3.w * s3v + b3v);
    }
    *(float4*)(partS + pg * 64 + c0) = m4;
    __syncthreads();

    if (t < 64) {
        float v = partS[t];
#pragma unroll
        for (int pg2 = 1; pg2 < 32; pg2++) v = fmaxf(v, partS[pg2 * 64 + t]);
        int b = (blockIdx.x * 1024) >> 16;       // batch (uniform per block)
        atomicMax(&g_partI[b * 64 + t], __float_as_int(v));   // v >= 0
    }
}

// ---------------------------------------------------------------------------
// K3: fused per-point MLPs -> pre[b,n,32] fp16, TNet head inline (measured ~16us).
// ---------------------------------------------------------------------------
__global__ void __launch_bounds__(128) k_pointwise(
    const float* __restrict__ feature, const float* __restrict__ xyz,
    const float* __restrict__ tW3, const float* __restrict__ ts3, const float* __restrict__ tb3,
    const float* __restrict__ tW4, const float* __restrict__ tb4,
    const float* __restrict__ W1, const float* __restrict__ s1, const float* __restrict__ b1,
    const float* __restrict__ W2, const float* __restrict__ s2, const float* __restrict__ b2,
    const float* __restrict__ W3, const float* __restrict__ s3, const float* __restrict__ b3)
{
    __shared__ float4 sW2f4[256];        // W2 32x32
    __shared__ float4 sW3f4[256];        // W3 rows 0..31
    __shared__ float4 sW3x4[24];         // W3 rows 32..34 (xyz part)
    __shared__ float  sS2[32], sB2[32], sS3[32], sB3[32];
    __shared__ float  sW1[9], sTM[9], sS1[3], sB1[3];
    __shared__ float  hmax[64], h3s[16];
    __shared__ uint4  sStage[640];       // pre stage: 128 pts x 4 uint4, stride 5
    int t   = threadIdx.x;
    int gp0 = blockIdx.x * 128;
    int b   = gp0 >> 16;
    { const float4* W2v = (const float4*)W2;
      sW2f4[t] = W2v[t]; sW2f4[128 + t] = W2v[128 + t]; }
    { const float4* W3v = (const float4*)W3;
      sW3f4[t] = W3v[t]; sW3f4[128 + t] = W3v[128 + t];
      if (t < 24) sW3x4[t] = W3v[256 + t]; }
    if (t < 32) { sS2[t] = s2[t]; sB2[t] = b2[t]; sS3[t] = s3[t]; sB3[t] = b3[t]; }
    if (t < 9)  sW1[t] = W1[t];
    if (t < 3)  { sS1[t] = s1[t]; sB1[t] = b1[t]; }
    // TNet head, inline: hmax (direct read) -> h3 -> tmat
    if (t >= 64 && t < 128) {
        int c = t - 64;
        hmax[c] = __int_as_float(g_partI[b * 64 + c]);
    }
    __syncthreads();
    if (t < 16) {
        float a = 0.f;
#pragma unroll
        for (int i = 0; i < 64; i++) a += hmax[i] * tW3[i * 16 + t];
        h3s[t] = fmaxf(a * ts3[t] + tb3[t], 0.f);
    }
    __syncthreads();
    if (t < 9) {
        float a = 0.f;
#pragma unroll
        for (int i = 0; i < 16; i++) a += h3s[i] * tW4[i * 9 + t];
        a += tb4[t];
        if (t == 0 || t == 4 || t == 8) a += 1.0f;   // + eye(3)
        sTM[t] = a;
    }
    __syncthreads();

    int gp = gp0 + t;
    int n  = gp & (NN - 1);

    // f_xyz = relu(((xyz @ t3x3) @ W1) * s1 + b1)
    float x0 = xyz[gp * 3 + 0], x1 = xyz[gp * 3 + 1], x2 = xyz[gp * 3 + 2];
    float v0 = x0 * sTM[0] + x1 * sTM[3] + x2 * sTM[6];
    float v1 = x0 * sTM[1] + x1 * sTM[4] + x2 * sTM[7];
    float v2 = x0 * sTM[2] + x1 * sTM[5] + x2 * sTM[8];
    float fx0 = fmaxf((v0 * sW1[0] + v1 * sW1[3] + v2 * sW1[6]) * sS1[0] + sB1[0], 0.f);
    float fx1 = fmaxf((v0 * sW1[1] + v1 * sW1[4] + v2 * sW1[7]) * sS1[1] + sB1[1], 0.f);
    float fx2 = fmaxf((v0 * sW1[2] + v1 * sW1[5] + v2 * sW1[8]) * sS1[2] + sB1[2], 0.f);

    // f_nei = relu((feat @ W2) * s2 + b2)
    const float* fbase = feature + (size_t)b * DD * NN + n;
    float acc[32];
#pragma unroll
    for (int c = 0; c < 32; c++) acc[c] = 0.f;
#pragma unroll
    for (int i = 0; i < 32; i++) {
        float v = fbase[(size_t)i * NN];
#pragma unroll
        for (int c4 = 0; c4 < 8; c4++) {
            float4 w = sW2f4[i * 8 + c4];
            acc[c4 * 4 + 0] += v * w.x; acc[c4 * 4 + 1] += v * w.y;
            acc[c4 * 4 + 2] += v * w.z; acc[c4 * 4 + 3] += v * w.w;
        }
    }
    float fn[32];
#pragma unroll
    for (int c = 0; c < 32; c++) fn[c] = fmaxf(acc[c] * sS2[c] + sB2[c], 0.f);

    // pre = relu((concat(fn, fx) @ W3) * s3 + b3)
#pragma unroll
    for (int c = 0; c < 32; c++) acc[c] = 0.f;
#pragma unroll
    for (int i = 0; i < 32; i++) {
        float v = fn[i];
#pragma unroll
        for (int c4 = 0; c4 < 8; c4++) {
            float4 w = sW3f4[i * 8 + c4];
            acc[c4 * 4 + 0] += v * w.x; acc[c4 * 4 + 1] += v * w.y;
            acc[c4 * 4 + 2] += v * w.z; acc[c4 * 4 + 3] += v * w.w;
        }
    }
#pragma unroll
    for (int c4 = 0; c4 < 8; c4++) {
        float4 wa = sW3x4[c4], wb = sW3x4[8 + c4], wc = sW3x4[16 + c4];
        acc[c4 * 4 + 0] += fx0 * wa.x + fx1 * wb.x + fx2 * wc.x;
        acc[c4 * 4 + 1] += fx0 * wa.y + fx1 * wb.y + fx2 * wc.y;
        acc[c4 * 4 + 2] += fx0 * wa.z + fx1 * wb.z + fx2 * wc.z;
        acc[c4 * 4 + 3] += fx0 * wa.w + fx1 * wb.w + fx2 * wc.w;
    }
    unsigned uh[16];
#pragma unroll
    for (int c2 = 0; c2 < 16; c2++) {
        float a  = fmaxf(acc[2 * c2]     * sS3[2 * c2]     + sB3[2 * c2],     0.f);
        float bb = fmaxf(acc[2 * c2 + 1] * sS3[2 * c2 + 1] + sB3[2 * c2 + 1], 0.f);
        __half2 h = __floats2half2_rn(a, bb);
        uh[c2] = *reinterpret_cast<unsigned*>(&h);
    }
#pragma unroll
    for (int q = 0; q < 4; q++) {
        uint4 o;
        o.x = uh[q * 4 + 0]; o.y = uh[q * 4 + 1]; o.z = uh[q * 4 + 2]; o.w = uh[q * 4 + 3];
        sStage[t * 5 + q] = o;
    }
    __syncthreads();

    // coalesced uint4 writeout of pre
    uint4* outp = g_preh4 + (size_t)gp0 * 4;
#pragma unroll
    for (int r = 0; r < 4; r++) {
        int i = r * 128 + t;             // i = p*4 + q
        outp[i] = sStage[(i >> 2) * 5 + (i & 3)];
    }
}

// ---------------------------------------------------------------------------
// K4 (v6): R16 structure + conflict-free feat staging: 4 iterations of
// (4 coalesced LDG.32 -> 1 STS.128). STS.128 phases hit distinct bank-quads
// (4p mod 32 distinct for 8 consecutive p) -> structural-minimum wavefronts,
// removing the 4-way scalar-STS conflict (~64 wf/thread).
// ---------------------------------------------------------------------------
__global__ void __launch_bounds__(256) k_gather_final(
    const float* __restrict__ feature, const int* __restrict__ nidx,
    const float* __restrict__ W4, const float* __restrict__ s4, const float* __restrict__ b4,
    float* __restrict__ out)
{
    __shared__ float4 sW4f4[512];        // W4 64x32 (rows 0..31 feat, 32..63 fcat)
    __shared__ float  sS4[32], sB4[32];
    __shared__ float4 featS4[128 * 9];   // feat rows [p][c], stride 36 floats
    __shared__ float4 fcatS4[128 * 9];   // max-pooled rows
    float* featS = (float*)featS4;
    float* fcatS = (float*)fcatS4;
    int t = threadIdx.x;
    sW4f4[t] = ((const float4*)W4)[t];
    sW4f4[256 + t] = ((const float4*)W4)[256 + t];
    if (t < 32) { sS4[t] = s4[t]; sB4[t] = b4[t]; }

    int gp0 = blockIdx.x * 128;
    int b   = gp0 >> 16;
    int n0  = gp0 & (NN - 1);

    // stage feat: 4 x (4 coalesced LDG + 1 conflict-free STS.128)
    const float* fbase = feature + (size_t)b * DD * NN + n0;
#pragma unroll
    for (int r = 0; r < 4; r++) {
        int i  = r * 256 + t;            // i = c4*128 + p
        int c4 = i >> 7, p = i & 127;
        const float* fp = fbase + (size_t)(c4 * 4) * NN + p;
        float4 v = make_float4(fp[0], fp[NN], fp[2 * (size_t)NN], fp[3 * (size_t)NN]);
        featS4[p * 9 + c4] = v;
    }

    // cooperative gather-max: 4 lanes/point, 2 passes of 64 points
    {
        int lane = t & 31;
        int warp = t >> 5;               // 0..7
        int cl   = lane & 3;
        int mul  = g_idx64 ? 2 : 1;
        const uint4* pre4 = g_preh4 + (size_t)b * NN * 4;
#pragma unroll
        for (int r = 0; r < 2; r++) {
            int p  = r * 64 + warp * 8 + (lane >> 2);
            int gp = gp0 + p;
            const int* ib = nidx + (size_t)gp * KK * mul;
            int j0 = ib[cl * mul];
            int j1 = ib[(cl + 4) * mul];
            int j2 = ib[(cl + 8) * mul];
            int j3 = ib[(cl + 12) * mul];
            __half2 a0 = __half2half2(__ushort_as_half(0));
            __half2 a1 = a0, a2 = a0, a3 = a0;   // pre >= 0, so 0-init exact
#pragma unroll
            for (int k = 0; k < KK; k++) {
                int jr = (k < 8) ? ((k < 4) ? j0 : j1) : ((k < 12) ? j2 : j3);
                int j  = __shfl_sync(0xffffffffu, jr, k & 3, 4);
                uint4 v = pre4[(size_t)j * 4 + cl];
                a0 = __hmax2(a0, *reinterpret_cast<__half2*>(&v.x));
                a1 = __hmax2(a1, *reinterpret_cast<__half2*>(&v.y));
                a2 = __hmax2(a2, *reinterpret_cast<__half2*>(&v.z));
                a3 = __hmax2(a3, *reinterpret_cast<__half2*>(&v.w));
            }
            float2 f0 = __half22float2(a0), f1 = __half22float2(a1);
            float2 f2 = __half22float2(a2), f3 = __half22float2(a3);
            float4* row = (float4*)(fcatS + p * 36);
            row[cl * 2 + 0] = make_float4(f0.x, f0.y, f1.x, f1.y);
            row[cl * 2 + 1] = make_float4(f2.x, f2.y, f3.x, f3.y);
        }
    }
    __syncthreads();

    // MLP: thread = (4 consecutive points, 4 channels), K=64 (feat + fcat).
    int pq = t >> 3, g = t & 7;          // pq: 0..31, 4 points each
    int p0 = pq * 4;
    u64 aLo[4] = {0ull, 0ull, 0ull, 0ull}, aHi[4] = {0ull, 0ull, 0ull, 0ull};
    {
        const ulonglong2* w4u = (const ulonglong2*)sW4f4;
#pragma unroll
        for (int i4 = 0; i4 < 16; i4++) {
            ulonglong2 w0 = w4u[(i4 * 4 + 0) * 8 + g];
            ulonglong2 w1 = w4u[(i4 * 4 + 1) * 8 + g];
            ulonglong2 w2 = w4u[(i4 * 4 + 2) * 8 + g];
            ulonglong2 w3 = w4u[(i4 * 4 + 3) * 8 + g];
            const float* src = (i4 < 8) ? featS : fcatS;
            int i4r = (i4 < 8) ? i4 : (i4 - 8);
#pragma unroll
            for (int q = 0; q < 4; q++) {
                float4 f = ((const float4*)(src + (p0 + q) * 36))[i4r];
                u64 v;
                v = pk2(f.x, f.x); aLo[q] = ffma2(v, w0.x, aLo[q]); aHi[q] = ffma2(v, w0.y, aHi[q]);
                v = pk2(f.y, f.y); aLo[q] = ffma2(v, w1.x, aLo[q]); aHi[q] = ffma2(v, w1.y, aHi[q]);
                v = pk2(f.z, f.z); aLo[q] = ffma2(v, w2.x, aLo[q]); aHi[q] = ffma2(v, w2.y, aHi[q]);
                v = pk2(f.w, f.w); aLo[q] = ffma2(v, w3.x, aLo[q]); aHi[q] = ffma2(v, w3.y, aHi[q]);
            }
        }
    }

    // epilogue: unpack to (channel x 4 points), scale+bias+relu, STG.128
    {
        int c0 = g * 4;
        float x[4][4];
#pragma unroll
        for (int q = 0; q < 4; q++) {
            up2(aLo[q], x[q][0], x[q][1]);
            up2(aHi[q], x[q][2], x[q][3]);
        }
        float* ob = out + (size_t)b * DD * NN + n0 + p0;
#pragma unroll
        for (int c = 0; c < 4; c++) {
            float s = sS4[c0 + c], bi = sB4[c0 + c];
            float4 o = make_float4(fmaxf(x[0][c] * s + bi, 0.f),
                                   fmaxf(x[1][c] * s + bi, 0.f),
                                   fmaxf(x[2][c] * s + bi, 0.f),
                                   fmaxf(x[3][c] * s + bi, 0.f));
            *(float4*)(ob + (size_t)(c0 + c) * NN) = o;
        }
    }
}

// ---------------------------------------------------------------------------

extern "C" void kernel_launch(void* const* d_in, const int* in_sizes, int n_in,
                              void* d_out, int out_size) {
    const float* feature = (const float*)d_in[0];
    const float* xyz     = (const float*)d_in[1];
    const int*   nidx    = (const int*)d_in[2];
    const float* tW1 = (const float*)d_in[3];  const float* ts1 = (const float*)d_in[4];  const float* tb1 = (const float*)d_in[5];
    const float* tW2 = (const float*)d_in[6];  const float* ts2 = (const float*)d_in[7];  const float* tb2 = (const float*)d_in[8];
    const float* tW3 = (const float*)d_in[9];  const float* ts3 = (const float*)d_in[10]; const float* tb3 = (const float*)d_in[11];
    const float* tW4 = (const float*)d_in[12]; const float* tb4 = (const float*)d_in[13];
    const float* W1  = (const float*)d_in[14]; const float* s1  = (const float*)d_in[15]; const float* b1  = (const float*)d_in[16];
    const float* W2  = (const float*)d_in[17]; const float* s2  = (const float*)d_in[18]; const float* b2  = (const float*)d_in[19];
    const float* W3  = (const float*)d_in[20]; const float* s3  = (const float*)d_in[21]; const float* b3  = (const float*)d_in[22];
    const float* W4  = (const float*)d_in[23]; const float* s4  = (const float*)d_in[24]; const float* b4  = (const float*)d_in[25];
    float* out = (float*)d_out;

    k_zero<<<1, 128>>>();
    k_tnet_reduce<<<128, 512>>>(xyz, nidx, tW1, ts1, tb1, tW2, ts2, tb2);
    k_pointwise<<<(BB * NN) / 128, 128>>>(feature, xyz, tW3, ts3, tb3, tW4, tb4,
                                          W1, s1, b1, W2, s2, b2, W3, s3, b3);
    k_gather_final<<<(BB * NN) / 128, 256>>>(feature, nidx, W4, s4, b4, out);
}